// round 5
// baseline (speedup 1.0000x reference)
#include <cuda_runtime.h>
#include <cuda_bf16.h>

// HybridQuanvolutionFraudNet — reference ends with log_softmax over a
// singleton axis ([B,1]): identically zero for every element, independent of
// all inputs. Exact output: zeros([2048,1], float32) = 8192 zero BYTES.
//
// Perf status: four kernel bodies (grid=8 scalar; grid=1 pred/unpred STG.128)
// all pin at 3.20-3.42 us kernel time, every pipe ~0% — we are at the
// one-kernel-node graph-replay floor. This round swaps the node TYPE:
// a cudaMemsetAsync on the capture stream records a memset graph node
// instead of a kernel node, skipping CTA dispatch/drain entirely.
// float 0.0f is bytewise 0x00, so memset(0) is bit-exact.

// Kernel retained only as a fallback path (not used when memset succeeds).
__global__ void HybridQuanvolutionFraudNet_65481071399590_zero_any(float* __restrict__ out, int n) {
    int i = blockIdx.x * blockDim.x + threadIdx.x;
    if (i < n) out[i] = 0.0f;
}

extern "C" void kernel_launch(void* const* d_in, const int* in_sizes, int n_in,
                              void* d_out, int out_size) {
    (void)d_in; (void)in_sizes; (void)n_in;
    // Async memset on the capture (legacy default) stream -> memset graph node.
    cudaError_t err = cudaMemsetAsync(d_out, 0, (size_t)out_size * sizeof(float), 0);
    if (err != cudaSuccess) {
        // Defensive: fall back to a kernel node if memset capture is rejected.
        int threads = 256;
        int blocks = (out_size + threads - 1) / threads;
        HybridQuanvolutionFraudNet_65481071399590_zero_any<<<blocks, threads>>>((float*)d_out, out_size);
    }
}

// round 7
// speedup vs baseline: 1.1064x; 1.1064x over previous
#include <cuda_runtime.h>
#include <cuda_bf16.h>

// HybridQuanvolutionFraudNet — reference ends with log_softmax over a
// singleton axis ([B,1]): x - logsumexp(x) == 0 elementwise when the axis has
// size 1, for ANY input. The entire quanvolution + MLP pipeline is
// algebraically dead. Exact output: zeros([2048,1], float32); rel_err = 0 on
// every seed.
//
// Perf status — floor fully mapped:
//   * kernel-node replay cost is body-invariant: grid=8 scalar STG, grid=1
//     predicated STG.128, grid=1 unconditional STG.128 all measure
//     3.20-3.42 us kernel time, every pipe ~0%.
//   * memset graph node (cudaMemsetAsync) is SLOWER (6.66 us): CE fill path
//     loses to an SM kernel node at 8 KB.
// => single kernel node, grid=1 x 512, one STG.E.128 per thread. Terminal.
// (R6 failure was infra: "device busy" in harness init, pre-kernel.)

__global__ void __launch_bounds__(512, 1)
HybridQuanvolutionFraudNet_65481071399590_kernel(float4* __restrict__ out, int n4) {
    int i = threadIdx.x;
    if (i < n4) out[i] = make_float4(0.f, 0.f, 0.f, 0.f);  // 512 x STG.E.128 = 8192 B
}

// Defensive fallback for a non-multiple-of-4 out_size (not expected here).
__global__ void HybridQuanvolutionFraudNet_65481071399590_zero_any(float* __restrict__ out, int n) {
    int i = blockIdx.x * blockDim.x + threadIdx.x;
    if (i < n) out[i] = 0.0f;
}

extern "C" void kernel_launch(void* const* d_in, const int* in_sizes, int n_in,
                              void* d_out, int out_size) {
    (void)d_in; (void)in_sizes; (void)n_in;
    if ((out_size & 3) == 0 && out_size <= 4 * 512) {
        HybridQuanvolutionFraudNet_65481071399590_kernel<<<1, 512>>>((float4*)d_out, out_size / 4);
    } else {
        int threads = 256;
        int blocks = (out_size + threads - 1) / threads;
        HybridQuanvolutionFraudNet_65481071399590_zero_any<<<blocks, threads>>>((float*)d_out, out_size);
    }
}

// round 9
// speedup vs baseline: 1.1620x; 1.0503x over previous
#include <cuda_runtime.h>
#include <cuda_bf16.h>

// HybridQuanvolutionFraudNet — reference ends with log_softmax over a
// singleton axis ([B,1]): x - logsumexp(x) == 0 elementwise when the axis has
// size 1, for ANY input. The entire quanvolution + MLP pipeline is
// algebraically dead. Exact output: zeros([2048,1], float32); rel_err = 0 on
// every seed.
//
// Perf status — floor fully mapped over 7 rounds:
//   * kernel-node replay cost is body-invariant: four structurally different
//     bodies all measure 3.2-3.7 us kernel time, every pipe ~0%.
//   * memset graph node is SLOWER (6.66 us): CE fill loses at 8 KB.
//   * bench dur for THIS exact kernel: 4.608, 4.608, 5.600, 4.864, 6.016 us
//     => floor ~4.6 us with +-1.5 us run-to-run jitter. No removable work
//     remains (one wave, 16 warps, one STG.E.128 each). Terminal kernel.

__global__ void __launch_bounds__(512, 1)
HybridQuanvolutionFraudNet_65481071399590_kernel(float4* __restrict__ out, int n4) {
    int i = threadIdx.x;
    if (i < n4) out[i] = make_float4(0.f, 0.f, 0.f, 0.f);  // 512 x STG.E.128 = 8192 B
}

// Defensive fallback for a non-multiple-of-4 out_size (not expected here).
__global__ void HybridQuanvolutionFraudNet_65481071399590_zero_any(float* __restrict__ out, int n) {
    int i = blockIdx.x * blockDim.x + threadIdx.x;
    if (i < n) out[i] = 0.0f;
}

extern "C" void kernel_launch(void* const* d_in, const int* in_sizes, int n_in,
                              void* d_out, int out_size) {
    (void)d_in; (void)in_sizes; (void)n_in;
    if ((out_size & 3) == 0 && out_size <= 4 * 512) {
        HybridQuanvolutionFraudNet_65481071399590_kernel<<<1, 512>>>((float4*)d_out, out_size / 4);
    } else {
        int threads = 256;
        int blocks = (out_size + threads - 1) / threads;
        HybridQuanvolutionFraudNet_65481071399590_zero_any<<<blocks, threads>>>((float*)d_out, out_size);
    }
}

// round 10
// speedup vs baseline: 1.3775x; 1.1854x over previous
#include <cuda_runtime.h>
#include <cuda_bf16.h>

// HybridQuanvolutionFraudNet — reference ends with log_softmax over a
// singleton axis ([B,1]): x - logsumexp(x) == 0 elementwise when the axis has
// size 1, for ANY input. The entire quanvolution + MLP pipeline is
// algebraically dead. Exact output: zeros([2048,1], float32); rel_err = 0 on
// every seed.
//
// Perf status — floor fully mapped over 9 rounds. TERMINAL KERNEL.
//   * kernel-node replay cost is body-invariant: four structurally different
//     bodies all measure 3.2-3.7 us kernel time, every pipe ~0%.
//   * memset graph node is SLOWER (6.66 us): CE fill loses at 8 KB.
//   * bench dur for THIS exact body across six clean runs:
//     4.608, 4.608, 5.600, 4.864, 6.016, 5.728 us
//     => floor ~4.6 us center, +-1.5 us environmental jitter; ncu kernel time
//     itself drifts 3.2-3.7 us for byte-identical SASS.
//   * No removable work remains: one wave, 16 warps, one STG.E.128 each
//     writing the exact 8192-byte output. Expected value of any edit: zero.

__global__ void __launch_bounds__(512, 1)
HybridQuanvolutionFraudNet_65481071399590_kernel(float4* __restrict__ out, int n4) {
    int i = threadIdx.x;
    if (i < n4) out[i] = make_float4(0.f, 0.f, 0.f, 0.f);  // 512 x STG.E.128 = 8192 B
}

// Defensive fallback for a non-multiple-of-4 out_size (not expected here).
__global__ void HybridQuanvolutionFraudNet_65481071399590_zero_any(float* __restrict__ out, int n) {
    int i = blockIdx.x * blockDim.x + threadIdx.x;
    if (i < n) out[i] = 0.0f;
}

extern "C" void kernel_launch(void* const* d_in, const int* in_sizes, int n_in,
                              void* d_out, int out_size) {
    (void)d_in; (void)in_sizes; (void)n_in;
    if ((out_size & 3) == 0 && out_size <= 4 * 512) {
        HybridQuanvolutionFraudNet_65481071399590_kernel<<<1, 512>>>((float4*)d_out, out_size / 4);
    } else {
        int threads = 256;
        int blocks = (out_size + threads - 1) / threads;
        HybridQuanvolutionFraudNet_65481071399590_zero_any<<<blocks, threads>>>((float*)d_out, out_size);
    }
}